// round 4
// baseline (speedup 1.0000x reference)
#include <cuda_runtime.h>
#include <cstdint>

// StructAttentionLayer: B=16384, A=50, D=256, fp32. HBM-bound (873MB read once).
// R4: persistent CTAs (2/SM), double-buffered cp.async.bulk pipeline.
// Buffer p holds tile b_k while b_{k+1} streams into p^1; prefetch b_{k+2}
// is issued as soon as p is consumed. No CTA-turnover latency bubbles.

#define A_NUM 50
#define D_DIM 256
#define ALPHA 0.2f
#define B_TOT 16384
#define TILE_BYTES (A_NUM * D_DIM * 4)          // 51200
#define ENT_BYTES  (D_DIM * 4)                  // 1024
#define TX_BYTES   (TILE_BYTES + ENT_BYTES)     // 52224
#define BUF_FLOATS (TX_BYTES / 4)               // 13056
#define DYN_SMEM   (2 * TX_BYTES)               // 104448

__global__ __launch_bounds__(256, 2)
void struct_attn_kernel(const float* __restrict__ attrs,
                        const float* __restrict__ ent,
                        const float* __restrict__ aa,
                        float* __restrict__ out,
                        int B)
{
    extern __shared__ __align__(128) float sm[];
    // buf p: tile at sm + p*BUF_FLOATS, ent row at +A_NUM*D_DIM
    __shared__ float e_s[A_NUM + 2];
    __shared__ __align__(8) unsigned long long mbar[2];

    const int t    = threadIdx.x;
    const int warp = t >> 5;
    const int lane = t & 31;
    const int G    = gridDim.x;

    const uint32_t mb0 = (uint32_t)__cvta_generic_to_shared(&mbar[0]);
    const uint32_t mb1 = (uint32_t)__cvta_generic_to_shared(&mbar[1]);

    if (t == 0) {
        asm volatile("mbarrier.init.shared.b64 [%0], 1;" :: "r"(mb0) : "memory");
        asm volatile("mbarrier.init.shared.b64 [%0], 1;" :: "r"(mb1) : "memory");
    }
    __syncthreads();

    // Weight vectors, register-resident for the whole persistent run.
    const float4* aa4 = reinterpret_cast<const float4*>(aa);
    const float4 aw0 = aa4[lane];            // a_attr[ lane*4      ..]
    const float4 aw1 = aa4[32 + lane];       // a_attr[128 + lane*4 ..]
    const float4 ew0 = aa4[64 + lane];       // a_ent
    const float4 ew1 = aa4[96 + lane];

    // Prologue: prefetch first two tiles.
    if (t == 0) {
#pragma unroll
        for (int k = 0; k < 2; k++) {
            const long long b = (long long)blockIdx.x + (long long)k * G;
            if (b < B) {
                const uint32_t mb = k ? mb1 : mb0;
                const uint32_t ta = (uint32_t)__cvta_generic_to_shared(sm + k * BUF_FLOATS);
                asm volatile("mbarrier.arrive.expect_tx.shared.b64 _, [%0], %1;"
                             :: "r"(mb), "r"((uint32_t)TX_BYTES) : "memory");
                asm volatile("cp.async.bulk.shared::cta.global.mbarrier::complete_tx::bytes "
                             "[%0], [%1], %2, [%3];"
                             :: "r"(ta), "l"(attrs + b * (A_NUM * D_DIM)),
                                "r"((uint32_t)TILE_BYTES), "r"(mb) : "memory");
                asm volatile("cp.async.bulk.shared::cta.global.mbarrier::complete_tx::bytes "
                             "[%0], [%1], %2, [%3];"
                             :: "r"(ta + TILE_BYTES), "l"(ent + b * D_DIM),
                                "r"((uint32_t)ENT_BYTES), "r"(mb) : "memory");
            }
        }
    }

    uint32_t ph0 = 0, ph1 = 0;   // phase parity per buffer

    int k = 0;
    for (long long b = blockIdx.x; b < B; b += G, k++) {
        const int p = k & 1;
        float* tile = sm + p * BUF_FLOATS;
        float* ents = tile + A_NUM * D_DIM;
        const uint32_t mb = p ? mb1 : mb0;
        const uint32_t myph = p ? ph1 : ph0;

        // Wait for this buffer's TMA (acquire).
        asm volatile(
            "{\n\t"
            ".reg .pred P;\n\t"
            "WL%=:\n\t"
            "mbarrier.try_wait.parity.acquire.cta.shared::cta.b64 P, [%0], %1, 0x989680;\n\t"
            "@P bra WD%=;\n\t"
            "bra WL%=;\n\t"
            "WD%=:\n\t"
            "}" :: "r"(mb), "r"(myph) : "memory");
        if (p) ph1 ^= 1; else ph0 ^= 1;

        // --- logits: warp w owns rows {w, w+8, ...} ---
        const float4* tile4 = reinterpret_cast<const float4*>(tile);
#pragma unroll
        for (int i = 0; i < 7; i++) {
            const int a = warp + 8 * i;
            if (a < A_NUM) {
                const float4 v0 = tile4[a * 64 + lane];
                const float4 v1 = tile4[a * 64 + 32 + lane];
                float s = v0.x * aw0.x + v0.y * aw0.y + v0.z * aw0.z + v0.w * aw0.w
                        + v1.x * aw1.x + v1.y * aw1.y + v1.z * aw1.z + v1.w * aw1.w;
                s += __shfl_xor_sync(0xffffffffu, s, 16);
                s += __shfl_xor_sync(0xffffffffu, s, 8);
                s += __shfl_xor_sync(0xffffffffu, s, 4);
                s += __shfl_xor_sync(0xffffffffu, s, 2);
                s += __shfl_xor_sync(0xffffffffu, s, 1);
                if (lane == 0) e_s[a] = s;
            }
        }
        // --- entity dot (warp 7 has only 6 rows) ---
        if (warp == 7) {
            const float4* e4 = reinterpret_cast<const float4*>(ents);
            const float4 ev0 = e4[lane];
            const float4 ev1 = e4[32 + lane];
            float pd = ev0.x * ew0.x + ev0.y * ew0.y + ev0.z * ew0.z + ev0.w * ew0.w
                     + ev1.x * ew1.x + ev1.y * ew1.y + ev1.z * ew1.z + ev1.w * ew1.w;
            pd += __shfl_xor_sync(0xffffffffu, pd, 16);
            pd += __shfl_xor_sync(0xffffffffu, pd, 8);
            pd += __shfl_xor_sync(0xffffffffu, pd, 4);
            pd += __shfl_xor_sync(0xffffffffu, pd, 2);
            pd += __shfl_xor_sync(0xffffffffu, pd, 1);
            if (lane == 0) e_s[A_NUM] = pd;
        }
        __syncthreads();

        // --- leaky-relu + softmax over 50 (warp 0), scaled by A_NUM ---
        if (warp == 0) {
            const float ed = e_s[A_NUM];
            float x0 = e_s[lane] + ed;
            x0 = (x0 > 0.f) ? x0 : ALPHA * x0;
            float x1 = -1e30f;
            if (lane < A_NUM - 32) {
                x1 = e_s[lane + 32] + ed;
                x1 = (x1 > 0.f) ? x1 : ALPHA * x1;
            }
            float m = fmaxf(x0, x1);
            m = fmaxf(m, __shfl_xor_sync(0xffffffffu, m, 16));
            m = fmaxf(m, __shfl_xor_sync(0xffffffffu, m, 8));
            m = fmaxf(m, __shfl_xor_sync(0xffffffffu, m, 4));
            m = fmaxf(m, __shfl_xor_sync(0xffffffffu, m, 2));
            m = fmaxf(m, __shfl_xor_sync(0xffffffffu, m, 1));
            const float q0 = __expf(x0 - m);
            const float q1 = (lane < A_NUM - 32) ? __expf(x1 - m) : 0.f;
            float ssum = q0 + q1;
            ssum += __shfl_xor_sync(0xffffffffu, ssum, 16);
            ssum += __shfl_xor_sync(0xffffffffu, ssum, 8);
            ssum += __shfl_xor_sync(0xffffffffu, ssum, 4);
            ssum += __shfl_xor_sync(0xffffffffu, ssum, 2);
            ssum += __shfl_xor_sync(0xffffffffu, ssum, 1);
            const float inv = (float)A_NUM / ssum;
            e_s[lane] = q0 * inv;
            if (lane < A_NUM - 32) e_s[lane + 32] = q1 * inv;
        }
        __syncthreads();

        // --- weighted sum: thread t owns output column t ---
        float a0 = 0.f, a1 = 0.f;
#pragma unroll
        for (int a = 0; a < A_NUM; a += 2) {
            a0 = fmaf(e_s[a],     tile[a * D_DIM + t],       a0);
            a1 = fmaf(e_s[a + 1], tile[(a + 1) * D_DIM + t], a1);
        }
        out[b * D_DIM + t] = a0 + a1;

        // Buffer p fully consumed; all threads done before refilling it.
        __syncthreads();

        // Prefetch tile k+2 into buffer p.
        if (t == 0) {
            const long long bn = b + 2LL * G;
            if (bn < B) {
                const uint32_t ta = (uint32_t)__cvta_generic_to_shared(tile);
                asm volatile("mbarrier.arrive.expect_tx.shared.b64 _, [%0], %1;"
                             :: "r"(mb), "r"((uint32_t)TX_BYTES) : "memory");
                asm volatile("cp.async.bulk.shared::cta.global.mbarrier::complete_tx::bytes "
                             "[%0], [%1], %2, [%3];"
                             :: "r"(ta), "l"(attrs + bn * (A_NUM * D_DIM)),
                                "r"((uint32_t)TILE_BYTES), "r"(mb) : "memory");
                asm volatile("cp.async.bulk.shared::cta.global.mbarrier::complete_tx::bytes "
                             "[%0], [%1], %2, [%3];"
                             :: "r"(ta + TILE_BYTES), "l"(ent + bn * D_DIM),
                                "r"((uint32_t)ENT_BYTES), "r"(mb) : "memory");
            }
        }
    }
}

extern "C" void kernel_launch(void* const* d_in, const int* in_sizes, int n_in,
                              void* d_out, int out_size)
{
    const float* attrs = (const float*)d_in[0];   // [16384, 50, 256]
    const float* ent   = (const float*)d_in[1];   // [16384, 256]
    const float* aa    = (const float*)d_in[2];   // [512, 1]
    float* out         = (float*)d_out;           // [16384, 256]

    static int attr_set = 0;
    if (!attr_set) {
        cudaFuncSetAttribute(struct_attn_kernel,
                             cudaFuncAttributeMaxDynamicSharedMemorySize, DYN_SMEM);
        attr_set = 1;
    }

    const int B = in_sizes[1] / D_DIM;            // 16384
    const int G = 296;                            // 2 CTAs per SM, persistent
    struct_attn_kernel<<<G, 256, DYN_SMEM>>>(attrs, ent, aa, out, B);
}